// round 16
// baseline (speedup 1.0000x reference)
#include <cuda_runtime.h>
#include <cuda_bf16.h>

// Grouped 1x7 conv (NCHW, groups=2, shared weights) + roll(H), tensor cores
// (m16n8k16 BF16, 3xBF16 split: hh + hl + lh, fp32 accumulate).
//
// SINGLE kernel, single graph node. K = kw*24 + 2*ic2 + e (kw 0..7, kw=7 zero;
// pair e over (ic2, ic2+12) at the same kw). This makes the in-kernel weight
// split perfectly coalesced (q = oc*7+kw consecutive) and shrinks the B tile
// to P[12][72] pairs. Per-chunk (kw, icb) offsets are compile-time constants.
// Block = (h, g, m-half): 48 oc x 56 px, 384 thr, 2 CTA/SM, 224 blocks.

#define Hdim 56
#define Wdim 56
#define HW   3136
#define ICg  24

#define SWP  100   // u64 stride per oc row of A tile (96 used)
#define SXP  72    // u64 stride per P row (needs >= 71)

#define W_TILE_BYTES (48 * SWP * 8)   // 38400
#define P_BYTES      (12 * SXP * 8)   // 6912

__device__ __forceinline__ unsigned bf16bits(float v) {
    return (unsigned)__bfloat16_as_ushort(__float2bfloat16_rn(v));
}

__device__ __forceinline__ uint2 split_pack(float v0, float v1) {
    unsigned h0 = bf16bits(v0);
    unsigned h1 = bf16bits(v1);
    float r0 = v0 - __bfloat162float(__ushort_as_bfloat16((unsigned short)h0));
    float r1 = v1 - __bfloat162float(__ushort_as_bfloat16((unsigned short)h1));
    unsigned l0 = bf16bits(r0);
    unsigned l1 = bf16bits(r1);
    return make_uint2(h0 | (h1 << 16), l0 | (l1 << 16));
}

__device__ __forceinline__ void mma_bf16(float c[4],
                                         unsigned a0, unsigned a1,
                                         unsigned a2, unsigned a3,
                                         unsigned b0, unsigned b1) {
    asm volatile(
        "mma.sync.aligned.m16n8k16.row.col.f32.bf16.bf16.f32 "
        "{%0,%1,%2,%3},{%4,%5,%6,%7},{%8,%9},{%0,%1,%2,%3};"
        : "+f"(c[0]), "+f"(c[1]), "+f"(c[2]), "+f"(c[3])
        : "r"(a0), "r"(a1), "r"(a2), "r"(a3), "r"(b0), "r"(b1));
}

__global__ __launch_bounds__(384, 2)
void conv1x7_bf4(const float* __restrict__ x, const float* __restrict__ w,
                 const int* __restrict__ shift, float* __restrict__ out)
{
    extern __shared__ char smem[];
    uint2* swq = (uint2*)smem;                       // [48][SWP] A pairs
    uint2* sxp = (uint2*)(smem + W_TILE_BYTES);      // [12][SXP] P pairs

    const int tid = threadIdx.x;
    const int h   = blockIdx.x;
    const int g   = blockIdx.y;
    const int mh  = blockIdx.z;      // oc in [mh*48, mh*48+48)

    // ---- A split: COALESCED direct gmem->smem ----
    // swq[oc_l][kw*12+ic2] = pack(w[ic2][oc][kw], w[ic2+12][oc][kw])
    const float* wg = w + mh * 336;  // + ic*672 + oc_l*7 + kw
    for (int i = tid; i < 4032; i += 384) {
        int ic2 = i / 336;
        int q   = i - ic2 * 336;     // q = oc_l*7 + kw (consecutive -> coalesced)
        int oc_l = q / 7;
        int kw   = q - oc_l * 7;
        float v0 = wg[ic2 * 672 + q];
        float v1 = wg[ic2 * 672 + q + 12 * 672];
        swq[oc_l * SWP + kw * 12 + ic2] = split_pack(v0, v1);
    }
    // zero kw=7 columns (j = 84..95)
    for (int i = tid; i < 576; i += 384) {
        int oc_l = i / 12;
        int ic2  = i - oc_l * 12;
        swq[oc_l * SWP + 84 + ic2] = make_uint2(0u, 0u);
    }

    // ---- P staging: sxp[ic2][p] = pack(x[ic2][h][p-3], x[ic2+12][h][p-3]) ----
    const float* xg = x + (size_t)g * (ICg * HW) + h * Wdim;
    for (int i = tid; i < 12 * SXP; i += 384) {      // 864
        int ic2 = i / SXP;
        int p   = i - ic2 * SXP;
        int wc  = p - 3;
        bool ok = (wc >= 0 && wc < Wdim);
        float v0 = ok ? xg[ic2 * HW + wc] : 0.f;
        float v1 = ok ? xg[(ic2 + 12) * HW + wc] : 0.f;
        sxp[ic2 * SXP + p] = split_pack(v0, v1);
    }
    __syncthreads();

    const int wid  = tid >> 5;        // 0..11
    const int mt   = wid >> 2;        // m-tile 0..2
    const int nq   = wid & 3;         // 0..3
    const int nf   = (nq == 3) ? 1 : 2;
    const int nt0  = nq * 2;          // frags nt0..nt0+nf-1 (7 total)
    const int lane = tid & 31;
    const int lg   = lane >> 2;       // 0..7
    const int lk   = lane & 3;        // 0..3

    const uint2* A0p = swq + (mt * 16 + lg) * SWP + lk;   // row lg
    const uint2* A1p = A0p + 8 * SWP;                     // row lg+8
    // B element: row = icb + lk, pixel = (nt0+f)*8 + lg + kw
    const uint2* Bbase = sxp + lk * SXP + nt0 * 8 + lg;

    float c[2][4];
    #pragma unroll
    for (int f = 0; f < 2; f++)
        #pragma unroll
        for (int q = 0; q < 4; q++) c[f][q] = 0.f;

    // per-chunk compile-time (icb, kw) for b0 (pr=8ks+lk) and b1 (pr=8ks+4+lk)
    const int ICB0[12] = {0,8,4,0,8,4,0,8,4,0,8,4};
    const int KW0 [12] = {0,0,1,2,2,3,4,4,5,6,6,7};
    const int ICB1[12] = {4,0,8,4,0,8,4,0,8,4,0,8};
    const int KW1 [12] = {0,1,1,2,3,3,4,5,5,6,7,7};

    #pragma unroll
    for (int ks = 0; ks < 12; ks++) {
        const int j = ks * 8;
        uint2 qa0 = A0p[j];                   // (hi,lo) A row lg,  pair col 8ks+lk
        uint2 qa1 = A1p[j];                   // row lg+8
        uint2 qa2 = A0p[j + 4];               // pair col 8ks+4+lk
        uint2 qa3 = A1p[j + 4];

        const uint2* b0p = Bbase + ICB0[ks] * SXP + KW0[ks];
        const uint2* b1p = Bbase + ICB1[ks] * SXP + KW1[ks];

        uint2 B0[2], B1[2];
        #pragma unroll
        for (int f = 0; f < 2; f++) {
            if (f < nf) {
                B0[f] = b0p[f * 8];
                B1[f] = b1p[f * 8];
            }
        }

        // hh
        #pragma unroll
        for (int f = 0; f < 2; f++)
            if (f < nf)
                mma_bf16(c[f], qa0.x, qa1.x, qa2.x, qa3.x, B0[f].x, B1[f].x);
        // hl
        #pragma unroll
        for (int f = 0; f < 2; f++)
            if (f < nf)
                mma_bf16(c[f], qa0.x, qa1.x, qa2.x, qa3.x, B0[f].y, B1[f].y);
        // lh
        #pragma unroll
        for (int f = 0; f < 2; f++)
            if (f < nf)
                mma_bf16(c[f], qa0.y, qa1.y, qa2.y, qa3.y, B0[f].x, B1[f].x);
    }

    // ---- roll + store ----
    const int s = *shift;
    int ho = (h + s) % Hdim;
    if (ho < 0) ho += Hdim;

    float* ob = out + (size_t)(g * 96 + mh * 48 + mt * 16 + lg) * HW
                    + ho * Wdim + (nt0 * 8 + 2 * lk);
    #pragma unroll
    for (int f = 0; f < 2; f++) {
        if (f < nf) {
            *(float2*)(ob + f * 8)          = make_float2(c[f][0], c[f][1]);
            *(float2*)(ob + 8 * HW + f * 8) = make_float2(c[f][2], c[f][3]);
        }
    }
}

extern "C" void kernel_launch(void* const* d_in, const int* in_sizes, int n_in,
                              void* d_out, int out_size)
{
    const float* x     = (const float*)d_in[0];
    const float* w     = (const float*)d_in[1];
    const int*   shift = (const int*)  d_in[2];
    float*       out   = (float*)d_out;

    const int smem_bytes = W_TILE_BYTES + P_BYTES;   // 45312
    cudaFuncSetAttribute(conv1x7_bf4,
                         cudaFuncAttributeMaxDynamicSharedMemorySize, smem_bytes);

    dim3 grid(Hdim, 2, 2);   // 56 x 2 x 2 = 224 blocks
    conv1x7_bf4<<<grid, 384, smem_bytes>>>(x, w, shift, out);
}